// round 1
// baseline (speedup 1.0000x reference)
#include <cuda_runtime.h>
#include <cuda_bf16.h>
#include <math.h>

// Problem constants
#define NN 50000
#define EE 600000
#define DD 128
#define LL 3
#define MTILES 391            // ceil(50000/128)
#define NPAD (MTILES * 128)   // 50048

// ---------------- device scratch (static; no runtime alloc) ----------------
__device__ float g_x [NPAD * DD];   // h + agg (GEMM1 input)
__device__ float g_y [NPAD * DD];   // GEMM1 output
__device__ float g_y2[NPAD * DD];   // GEMM2 output
__device__ float g_z [NPAD * DD];   // relu(bn2(y2))
__device__ float g_h [NPAD * DD];   // h between layers
__device__ float g_colsum[DD];
__device__ float g_colsq [DD];
__device__ float g_aArr  [DD];
__device__ float g_cArr  [DD];

// ---------------- kernels ----------------

// Copy h_in -> x, zero stats accumulators.
__global__ void prep_kernel(const float* __restrict__ h, float* __restrict__ x,
                            float* __restrict__ cs, float* __restrict__ cq)
{
    int gid = blockIdx.x * blockDim.x + threadIdx.x;
    if (gid < DD) { cs[gid] = 0.f; cq[gid] = 0.f; }
    if (gid < NN * (DD / 4))
        ((float4*)x)[gid] = ((const float4*)h)[gid];
}

// One warp per edge: x[dst] += w * h[src], vectorized f32x4 reductions.
__global__ void __launch_bounds__(256) scatter_kernel(
    const float* __restrict__ h, const int* __restrict__ src,
    const int* __restrict__ dst, const float* __restrict__ w,
    float* __restrict__ x)
{
    int warp = (blockIdx.x * blockDim.x + threadIdx.x) >> 5;
    int lane = threadIdx.x & 31;
    if (warp >= EE) return;
    int s   = __ldg(src + warp);
    int d   = __ldg(dst + warp);
    float we = __ldg(w + warp);
    float4 v = *(const float4*)(h + (size_t)s * DD + lane * 4);
    v.x *= we; v.y *= we; v.z *= we; v.w *= we;
    float* p = x + (size_t)d * DD + lane * 4;
    asm volatile("red.global.add.v4.f32 [%0], {%1,%2,%3,%4};"
                 :: "l"(p), "f"(v.x), "f"(v.y), "f"(v.z), "f"(v.w) : "memory");
}

// C[M,128] = act(A)[M,128] @ B[128,128], fp32.
// If useAffine: staged A element at feature k becomes relu(A*a[k] + c[k]).
// 128-row tiles, K chunked by 32, A transposed in smem, 8x8 micro-tiles.
__global__ void __launch_bounds__(256) gemm_kernel(
    const float* __restrict__ A, const float* __restrict__ B, float* __restrict__ C,
    const float* __restrict__ aAff, const float* __restrict__ cAff, int useAffine)
{
    __shared__ float As[32][132];   // [k][m], padded to avoid staging conflicts
    __shared__ float Bs[32][128];   // [k][n]

    const int t = threadIdx.x;
    const int mBase = blockIdx.x * 128;
    const int tr = t >> 4;          // 0..15 -> rows tr*8..tr*8+7
    const int tc = t & 15;          // 0..15 -> cols tc*8..tc*8+7

    float acc[8][8];
#pragma unroll
    for (int i = 0; i < 8; i++)
#pragma unroll
        for (int j = 0; j < 8; j++) acc[i][j] = 0.f;

    for (int kc = 0; kc < 4; kc++) {
        // stage A chunk: 128 rows x 32 cols, transposed
#pragma unroll
        for (int j = 0; j < 4; j++) {
            int idx  = t + 256 * j;        // 0..1023 float4 slots
            int row  = idx >> 3;           // 0..127
            int kloc = (idx & 7) * 4;      // 0,4,..,28
            float4 v = *(const float4*)(A + (size_t)(mBase + row) * DD + kc * 32 + kloc);
            if (useAffine) {
                float4 aa = *(const float4*)(aAff + kc * 32 + kloc);
                float4 cc = *(const float4*)(cAff + kc * 32 + kloc);
                v.x = fmaxf(fmaf(v.x, aa.x, cc.x), 0.f);
                v.y = fmaxf(fmaf(v.y, aa.y, cc.y), 0.f);
                v.z = fmaxf(fmaf(v.z, aa.z, cc.z), 0.f);
                v.w = fmaxf(fmaf(v.w, aa.w, cc.w), 0.f);
            }
            As[kloc + 0][row] = v.x;
            As[kloc + 1][row] = v.y;
            As[kloc + 2][row] = v.z;
            As[kloc + 3][row] = v.w;
        }
        // stage B chunk: 32 rows x 128 cols (row-major, coalesced)
#pragma unroll
        for (int j = 0; j < 4; j++) {
            int idx  = t + 256 * j;        // 0..1023 float4 slots
            int krow = idx >> 5;           // 0..31
            int c4   = (idx & 31) * 4;
            *(float4*)(&Bs[krow][c4]) =
                *(const float4*)(B + (size_t)(kc * 32 + krow) * DD + c4);
        }
        __syncthreads();

#pragma unroll
        for (int kk = 0; kk < 32; kk++) {
            float a[8], b[8];
            *(float4*)(a)     = *(const float4*)(&As[kk][tr * 8]);
            *(float4*)(a + 4) = *(const float4*)(&As[kk][tr * 8 + 4]);
            *(float4*)(b)     = *(const float4*)(&Bs[kk][tc * 8]);
            *(float4*)(b + 4) = *(const float4*)(&Bs[kk][tc * 8 + 4]);
#pragma unroll
            for (int i = 0; i < 8; i++)
#pragma unroll
                for (int j = 0; j < 8; j++)
                    acc[i][j] = fmaf(a[i], b[j], acc[i][j]);
        }
        __syncthreads();
    }

#pragma unroll
    for (int i = 0; i < 8; i++) {
        float* cp = C + (size_t)(mBase + tr * 8 + i) * DD + tc * 8;
        *(float4*)cp       = make_float4(acc[i][0], acc[i][1], acc[i][2], acc[i][3]);
        *(float4*)(cp + 4) = make_float4(acc[i][4], acc[i][5], acc[i][6], acc[i][7]);
    }
}

// Per-column sum / sumsq over the first NN rows (padded rows excluded).
__global__ void stats_kernel(const float* __restrict__ v,
                             float* __restrict__ cs, float* __restrict__ cq)
{
    int col = threadIdx.x;   // 128 threads
    float s = 0.f, q = 0.f;
    for (int m = blockIdx.x; m < NN; m += gridDim.x) {
        float x = v[(size_t)m * DD + col];
        s += x; q += x * x;
    }
    atomicAdd(cs + col, s);
    atomicAdd(cq + col, q);
}

// Convert stats + (g, b) into per-column affine (a, c); reset stats.
__global__ void finalize_kernel(const float* __restrict__ g, const float* __restrict__ b,
                                float* __restrict__ aOut, float* __restrict__ cOut,
                                float* __restrict__ cs, float* __restrict__ cq)
{
    int c = threadIdx.x;
    const float invN = 1.f / (float)NN;
    float mean = cs[c] * invN;
    float var  = cq[c] * invN - mean * mean;
    float a = g[c] * rsqrtf(var + 1e-5f);
    aOut[c] = a;
    cOut[c] = b[c] - mean * a;
    cs[c] = 0.f; cq[c] = 0.f;
}

// z = relu(y2 * a + c), with fused stats of z.
__global__ void zrelu_kernel(const float* __restrict__ y2, const float* __restrict__ aA,
                             const float* __restrict__ cA, float* __restrict__ z,
                             float* __restrict__ cs, float* __restrict__ cq)
{
    int col = threadIdx.x;   // 128 threads
    float a = aA[col], c = cA[col];
    float s = 0.f, q = 0.f;
    for (int m = blockIdx.x; m < NN; m += gridDim.x) {
        float v = fmaxf(fmaf(y2[(size_t)m * DD + col], a, c), 0.f);
        z[(size_t)m * DD + col] = v;
        s += v; q += v * v;
    }
    atomicAdd(cs + col, s);
    atomicAdd(cq + col, q);
}

// out = (z*a + c), optional relu; optionally also seed xnext for the next layer.
__global__ void apply_kernel(const float* __restrict__ z, const float* __restrict__ aA,
                             const float* __restrict__ cA, float* __restrict__ out,
                             float* __restrict__ xnext, int doRelu)
{
    int gid = blockIdx.x * blockDim.x + threadIdx.x;
    if (gid >= NN * (DD / 4)) return;
    int col4 = (gid & (DD / 4 - 1)) << 2;
    float4 v = ((const float4*)z)[gid];
    float4 A = *(const float4*)(aA + col4);
    float4 C = *(const float4*)(cA + col4);
    v.x = fmaf(v.x, A.x, C.x);
    v.y = fmaf(v.y, A.y, C.y);
    v.z = fmaf(v.z, A.z, C.z);
    v.w = fmaf(v.w, A.w, C.w);
    if (doRelu) {
        v.x = fmaxf(v.x, 0.f); v.y = fmaxf(v.y, 0.f);
        v.z = fmaxf(v.z, 0.f); v.w = fmaxf(v.w, 0.f);
    }
    ((float4*)out)[gid] = v;
    if (xnext) ((float4*)xnext)[gid] = v;
}

// ---------------- launch ----------------
extern "C" void kernel_launch(void* const* d_in, const int* in_sizes, int n_in,
                              void* d_out, int out_size)
{
    const float* h_in = (const float*)d_in[0];
    const int*   edges= (const int*)  d_in[1];
    const float* w    = (const float*)d_in[2];
    const float* W0s  = (const float*)d_in[3];
    const float* W1s  = (const float*)d_in[4];
    const float* bn1g = (const float*)d_in[5];
    const float* bn1b = (const float*)d_in[6];
    const float* bn2g = (const float*)d_in[7];
    const float* bn2b = (const float*)d_in[8];
    const float* bn3g = (const float*)d_in[9];
    const float* bn3b = (const float*)d_in[10];
    const int* src = edges;
    const int* dst = edges + EE;

    float *x, *y, *y2, *z, *h, *cs, *cq, *aArr, *cArr;
    cudaGetSymbolAddress((void**)&x,    g_x);
    cudaGetSymbolAddress((void**)&y,    g_y);
    cudaGetSymbolAddress((void**)&y2,   g_y2);
    cudaGetSymbolAddress((void**)&z,    g_z);
    cudaGetSymbolAddress((void**)&h,    g_h);
    cudaGetSymbolAddress((void**)&cs,   g_colsum);
    cudaGetSymbolAddress((void**)&cq,   g_colsq);
    cudaGetSymbolAddress((void**)&aArr, g_aArr);
    cudaGetSymbolAddress((void**)&cArr, g_cArr);

    const int EW_GRID = (NN * (DD / 4) + 255) / 256;   // 6250
    const int SC_GRID = (EE * 32 + 255) / 256;         // 75000 (1 warp/edge)

    prep_kernel<<<EW_GRID, 256>>>(h_in, x, cs, cq);

    for (int i = 0; i < LL; i++) {
        const float* hsrc = (i == 0) ? h_in : h;
        scatter_kernel<<<SC_GRID, 256>>>(hsrc, src, dst, w, x);

        gemm_kernel<<<MTILES, 256>>>(x, W0s + i * DD * DD, y, nullptr, nullptr, 0);
        stats_kernel<<<512, 128>>>(y, cs, cq);
        finalize_kernel<<<1, 128>>>(bn1g + i * DD, bn1b + i * DD, aArr, cArr, cs, cq);

        gemm_kernel<<<MTILES, 256>>>(y, W1s + i * DD * DD, y2, aArr, cArr, 1);
        stats_kernel<<<512, 128>>>(y2, cs, cq);
        finalize_kernel<<<1, 128>>>(bn2g + i * DD, bn2b + i * DD, aArr, cArr, cs, cq);

        zrelu_kernel<<<512, 128>>>(y2, aArr, cArr, z, cs, cq);
        finalize_kernel<<<1, 128>>>(bn3g + i * DD, bn3b + i * DD, aArr, cArr, cs, cq);

        int last = (i == LL - 1);
        apply_kernel<<<EW_GRID, 256>>>(z, aArr, cArr,
                                       last ? (float*)d_out : h,
                                       last ? nullptr : x,
                                       last ? 0 : 1);
    }
}

// round 3
// speedup vs baseline: 1.6000x; 1.6000x over previous
#include <cuda_runtime.h>
#include <cuda_bf16.h>
#include <cstdint>
#include <math.h>

// Problem constants
#define NN 50000
#define EE 600000
#define DD 128
#define LL 3
#define MTILES 391            // ceil(50000/128)
#define NPAD (MTILES * 128)   // 50048
#define SMP 136               // smem row stride (bf16 elems): conflict-free ldmatrix

// ---------------- device scratch (static; no runtime alloc) ----------------
__device__ float g_x [NPAD * DD];   // h + agg (GEMM1 input)
__device__ float g_y [NPAD * DD];   // GEMM1 output
__device__ float g_y2[NPAD * DD];   // GEMM2 output
__device__ float g_z [NPAD * DD];   // relu(bn2(y2))
__device__ float g_h [NPAD * DD];   // h between layers
__device__ float g_colsum[DD];
__device__ float g_colsq [DD];
__device__ float g_aArr  [DD];
__device__ float g_cArr  [DD];
__device__ __nv_bfloat16 g_bthi[DD * DD];  // W^T hi split, [n][k]
__device__ __nv_bfloat16 g_btlo[DD * DD];  // W^T lo split, [n][k]

// ---------------- warp-mma helpers (plain sm_100-safe PTX) ----------------
__device__ __forceinline__ uint32_t smem_u32(const void* p) {
    uint32_t a;
    asm("{ .reg .u64 t; cvta.to.shared.u64 t, %1; cvt.u32.u64 %0, t; }" : "=r"(a) : "l"(p));
    return a;
}
__device__ __forceinline__ void ldsm_x4(uint32_t* r, uint32_t addr) {
    asm volatile("ldmatrix.sync.aligned.m8n8.x4.shared.b16 {%0,%1,%2,%3}, [%4];"
                 : "=r"(r[0]), "=r"(r[1]), "=r"(r[2]), "=r"(r[3]) : "r"(addr));
}
__device__ __forceinline__ void ldsm_x2(uint32_t* r, uint32_t addr) {
    asm volatile("ldmatrix.sync.aligned.m8n8.x2.shared.b16 {%0,%1}, [%2];"
                 : "=r"(r[0]), "=r"(r[1]) : "r"(addr));
}
__device__ __forceinline__ void mma_bf16(float* d, const uint32_t* a, const uint32_t* b) {
    asm volatile("mma.sync.aligned.m16n8k16.row.col.f32.bf16.bf16.f32 "
                 "{%0,%1,%2,%3}, {%4,%5,%6,%7}, {%8,%9}, {%0,%1,%2,%3};"
                 : "+f"(d[0]), "+f"(d[1]), "+f"(d[2]), "+f"(d[3])
                 : "r"(a[0]), "r"(a[1]), "r"(a[2]), "r"(a[3]),
                   "r"(b[0]), "r"(b[1]));
}

// ---------------- kernels ----------------

// Copy h_in -> x, zero stats accumulators.
__global__ void prep_kernel(const float* __restrict__ h, float* __restrict__ x,
                            float* __restrict__ cs, float* __restrict__ cq)
{
    int gid = blockIdx.x * blockDim.x + threadIdx.x;
    if (gid < DD) { cs[gid] = 0.f; cq[gid] = 0.f; }
    if (gid < NN * (DD / 4))
        ((float4*)x)[gid] = ((const float4*)h)[gid];
}

// One warp per edge: x[dst] += w * h[src], vectorized f32x4 reductions.
__global__ void __launch_bounds__(256) scatter_kernel(
    const float* __restrict__ h, const int* __restrict__ src,
    const int* __restrict__ dst, const float* __restrict__ w,
    float* __restrict__ x)
{
    int warp = (blockIdx.x * blockDim.x + threadIdx.x) >> 5;
    int lane = threadIdx.x & 31;
    if (warp >= EE) return;
    int s   = __ldg(src + warp);
    int d   = __ldg(dst + warp);
    float we = __ldg(w + warp);
    float4 v = *(const float4*)(h + (size_t)s * DD + lane * 4);
    v.x *= we; v.y *= we; v.z *= we; v.w *= we;
    float* p = x + (size_t)d * DD + lane * 4;
    asm volatile("red.global.add.v4.f32 [%0], {%1,%2,%3,%4};"
                 :: "l"(p), "f"(v.x), "f"(v.y), "f"(v.z), "f"(v.w) : "memory");
}

// W[128][128] -> transposed hi/lo bf16 split: bt[n][k] = W[k][n]
__global__ void wprep_kernel(const float* __restrict__ W,
                             __nv_bfloat16* __restrict__ bhi,
                             __nv_bfloat16* __restrict__ blo)
{
    int idx = blockIdx.x * blockDim.x + threadIdx.x;
    if (idx >= DD * DD) return;
    int k = idx >> 7, n = idx & 127;
    float v = W[idx];
    __nv_bfloat16 h = __float2bfloat16(v);
    __nv_bfloat16 lo = __float2bfloat16(v - __bfloat162float(h));
    bhi[n * DD + k] = h;
    blo[n * DD + k] = lo;
}

// C[128-tile,128] = act(A) @ W via mma.sync bf16 hi/lo split (3 passes, fp32 acc).
// act = relu(A*a + c) when useAffine (applied in fp32 BEFORE the split).
__global__ void __launch_bounds__(256) gemm_mma_kernel(
    const float* __restrict__ A,
    const __nv_bfloat16* __restrict__ Bhi, const __nv_bfloat16* __restrict__ Blo,
    float* __restrict__ C,
    const float* __restrict__ aAff, const float* __restrict__ cAff, int useAffine)
{
    extern __shared__ __align__(16) char dyn[];
    __nv_bfloat16* sAhi = (__nv_bfloat16*)dyn;
    __nv_bfloat16* sAlo = sAhi + 128 * SMP;
    __nv_bfloat16* sBhi = sAlo + 128 * SMP;
    __nv_bfloat16* sBlo = sBhi + 128 * SMP;

    const int t = threadIdx.x, w = t >> 5, l = t & 31;
    const int mBase = blockIdx.x * 128;

    // ---- stage A: fp32 -> (affine+relu) -> bf16 hi/lo ----
    float4 aa, cc;
    if (useAffine) { aa = ((const float4*)aAff)[l]; cc = ((const float4*)cAff)[l]; }
#pragma unroll
    for (int it = 0; it < 16; it++) {
        int row = it * 8 + w;
        float4 v = ((const float4*)(A + (size_t)(mBase + row) * DD))[l];
        if (useAffine) {
            v.x = fmaxf(fmaf(v.x, aa.x, cc.x), 0.f);
            v.y = fmaxf(fmaf(v.y, aa.y, cc.y), 0.f);
            v.z = fmaxf(fmaf(v.z, aa.z, cc.z), 0.f);
            v.w = fmaxf(fmaf(v.w, aa.w, cc.w), 0.f);
        }
        __nv_bfloat162 h01 = __floats2bfloat162_rn(v.x, v.y);
        __nv_bfloat162 h23 = __floats2bfloat162_rn(v.z, v.w);
        __nv_bfloat162 l01 = __floats2bfloat162_rn(v.x - __low2float(h01), v.y - __high2float(h01));
        __nv_bfloat162 l23 = __floats2bfloat162_rn(v.z - __low2float(h23), v.w - __high2float(h23));
        int off = row * SMP + l * 4;
        *(uint2*)(sAhi + off) = make_uint2(*(uint32_t*)&h01, *(uint32_t*)&h23);
        *(uint2*)(sAlo + off) = make_uint2(*(uint32_t*)&l01, *(uint32_t*)&l23);
    }
    // ---- stage B: pre-split bf16 W^T[n][k], straight copy ----
#pragma unroll
    for (int it = 0; it < 16; it++) {
        int row = it * 8 + w;
        uint2 hv = ((const uint2*)(Bhi + (size_t)row * DD))[l];
        uint2 lv = ((const uint2*)(Blo + (size_t)row * DD))[l];
        int off = row * SMP + l * 4;
        *(uint2*)(sBhi + off) = hv;
        *(uint2*)(sBlo + off) = lv;
    }
    __syncthreads();

    // ---- compute: warp -> 32(M) x 64(N); 2 m-subtiles x 8 n-subtiles ----
    const int wm = (w >> 1) * 32;
    const int wn = (w & 1) * 64;
    float acc[16][4];
#pragma unroll
    for (int i = 0; i < 16; i++)
#pragma unroll
        for (int j = 0; j < 4; j++) acc[i][j] = 0.f;

    const int arow = l & 15;              // a-frag row within 16
    const int acol = (l >> 4) << 3;       // lanes 16-31 -> k+8
    const int brow = l & 7;               // b-frag row (n) within 8
    const int bcol = ((l >> 3) & 1) << 3; // lanes 8-15 -> k+8

#pragma unroll
    for (int pass = 0; pass < 3; pass++) {
        const __nv_bfloat16* pA = (pass == 2) ? sAlo : sAhi;
        const __nv_bfloat16* pB = (pass == 1) ? sBlo : sBhi;
#pragma unroll
        for (int kc = 0; kc < 8; kc++) {
            const int k0 = kc * 16;
            uint32_t afr[2][4];
#pragma unroll
            for (int sm = 0; sm < 2; sm++) {
                uint32_t addr = smem_u32(pA + (wm + sm * 16 + arow) * SMP + k0 + acol);
                ldsm_x4(afr[sm], addr);
            }
            uint32_t bfr[8][2];
#pragma unroll
            for (int sn = 0; sn < 8; sn++) {
                uint32_t addr = smem_u32(pB + (wn + sn * 8 + brow) * SMP + k0 + bcol);
                ldsm_x2(bfr[sn], addr);
            }
#pragma unroll
            for (int sm = 0; sm < 2; sm++)
#pragma unroll
                for (int sn = 0; sn < 8; sn++)
                    mma_bf16(acc[sm * 8 + sn], afr[sm], bfr[sn]);
        }
    }

    // ---- epilogue: d-frag -> C ----
    const int g = l >> 2, tq = l & 3;
#pragma unroll
    for (int sm = 0; sm < 2; sm++)
#pragma unroll
        for (int sn = 0; sn < 8; sn++) {
            float* p0 = C + (size_t)(mBase + wm + sm * 16 + g) * DD + wn + sn * 8 + tq * 2;
            *(float2*)p0            = make_float2(acc[sm * 8 + sn][0], acc[sm * 8 + sn][1]);
            *(float2*)(p0 + 8 * DD) = make_float2(acc[sm * 8 + sn][2], acc[sm * 8 + sn][3]);
        }
}

// Per-column sum/sumsq over the first NN rows. 256 thr: 8 rows x 32 float4 lanes.
__global__ void __launch_bounds__(256) stats_kernel(const float* __restrict__ v,
                                                    float* __restrict__ cs,
                                                    float* __restrict__ cq)
{
    __shared__ float shS[8][DD];
    __shared__ float shQ[8][DD];
    const int t = threadIdx.x;
    const int c4 = (t & 31) * 4;
    const int rg = t >> 5;
    float4 s = make_float4(0.f, 0.f, 0.f, 0.f), q = make_float4(0.f, 0.f, 0.f, 0.f);
    for (int m = blockIdx.x * 8 + rg; m < NN; m += gridDim.x * 8) {
        float4 x = *(const float4*)(v + (size_t)m * DD + c4);
        s.x += x.x; s.y += x.y; s.z += x.z; s.w += x.w;
        q.x += x.x * x.x; q.y += x.y * x.y; q.z += x.z * x.z; q.w += x.w * x.w;
    }
    *(float4*)&shS[rg][c4] = s;
    *(float4*)&shQ[rg][c4] = q;
    __syncthreads();
    if (t < DD) {
        float ts = 0.f, tq = 0.f;
#pragma unroll
        for (int i = 0; i < 8; i++) { ts += shS[i][t]; tq += shQ[i][t]; }
        atomicAdd(cs + t, ts);
        atomicAdd(cq + t, tq);
    }
}

// Convert stats + (g, b) into per-column affine (a, c); reset stats.
__global__ void finalize_kernel(const float* __restrict__ g, const float* __restrict__ b,
                                float* __restrict__ aOut, float* __restrict__ cOut,
                                float* __restrict__ cs, float* __restrict__ cq)
{
    int c = threadIdx.x;
    const float invN = 1.f / (float)NN;
    float mean = cs[c] * invN;
    float var  = cq[c] * invN - mean * mean;
    float a = g[c] * rsqrtf(var + 1e-5f);
    aOut[c] = a;
    cOut[c] = b[c] - mean * a;
    cs[c] = 0.f; cq[c] = 0.f;
}

// z = relu(y2*a + c) with fused stats of z.
__global__ void __launch_bounds__(256) zrelu_kernel(const float* __restrict__ y2,
                                                    const float* __restrict__ aA,
                                                    const float* __restrict__ cA,
                                                    float* __restrict__ z,
                                                    float* __restrict__ cs,
                                                    float* __restrict__ cq)
{
    __shared__ float shS[8][DD];
    __shared__ float shQ[8][DD];
    const int t = threadIdx.x;
    const int c4 = (t & 31) * 4;
    const int rg = t >> 5;
    float4 a = *(const float4*)(aA + c4);
    float4 c = *(const float4*)(cA + c4);
    float4 s = make_float4(0.f, 0.f, 0.f, 0.f), q = make_float4(0.f, 0.f, 0.f, 0.f);
    for (int m = blockIdx.x * 8 + rg; m < NN; m += gridDim.x * 8) {
        float4 v = *(const float4*)(y2 + (size_t)m * DD + c4);
        v.x = fmaxf(fmaf(v.x, a.x, c.x), 0.f);
        v.y = fmaxf(fmaf(v.y, a.y, c.y), 0.f);
        v.z = fmaxf(fmaf(v.z, a.z, c.z), 0.f);
        v.w = fmaxf(fmaf(v.w, a.w, c.w), 0.f);
        *(float4*)(z + (size_t)m * DD + c4) = v;
        s.x += v.x; s.y += v.y; s.z += v.z; s.w += v.w;
        q.x += v.x * v.x; q.y += v.y * v.y; q.z += v.z * v.z; q.w += v.w * v.w;
    }
    *(float4*)&shS[rg][c4] = s;
    *(float4*)&shQ[rg][c4] = q;
    __syncthreads();
    if (t < DD) {
        float ts = 0.f, tq = 0.f;
#pragma unroll
        for (int i = 0; i < 8; i++) { ts += shS[i][t]; tq += shQ[i][t]; }
        atomicAdd(cs + t, ts);
        atomicAdd(cq + t, tq);
    }
}

// out = (z*a + c), optional relu; optionally also seed xnext for the next layer.
__global__ void apply_kernel(const float* __restrict__ z, const float* __restrict__ aA,
                             const float* __restrict__ cA, float* __restrict__ out,
                             float* __restrict__ xnext, int doRelu)
{
    int gid = blockIdx.x * blockDim.x + threadIdx.x;
    if (gid >= NN * (DD / 4)) return;
    int col4 = (gid & (DD / 4 - 1)) << 2;
    float4 v = ((const float4*)z)[gid];
    float4 A = *(const float4*)(aA + col4);
    float4 C = *(const float4*)(cA + col4);
    v.x = fmaf(v.x, A.x, C.x);
    v.y = fmaf(v.y, A.y, C.y);
    v.z = fmaf(v.z, A.z, C.z);
    v.w = fmaf(v.w, A.w, C.w);
    if (doRelu) {
        v.x = fmaxf(v.x, 0.f); v.y = fmaxf(v.y, 0.f);
        v.z = fmaxf(v.z, 0.f); v.w = fmaxf(v.w, 0.f);
    }
    ((float4*)out)[gid] = v;
    if (xnext) ((float4*)xnext)[gid] = v;
}

// ---------------- launch ----------------
extern "C" void kernel_launch(void* const* d_in, const int* in_sizes, int n_in,
                              void* d_out, int out_size)
{
    const float* h_in = (const float*)d_in[0];
    const int*   edges= (const int*)  d_in[1];
    const float* w    = (const float*)d_in[2];
    const float* W0s  = (const float*)d_in[3];
    const float* W1s  = (const float*)d_in[4];
    const float* bn1g = (const float*)d_in[5];
    const float* bn1b = (const float*)d_in[6];
    const float* bn2g = (const float*)d_in[7];
    const float* bn2b = (const float*)d_in[8];
    const float* bn3g = (const float*)d_in[9];
    const float* bn3b = (const float*)d_in[10];
    const int* src = edges;
    const int* dst = edges + EE;

    float *x, *y, *y2, *z, *h, *cs, *cq, *aArr, *cArr;
    __nv_bfloat16 *bthi, *btlo;
    cudaGetSymbolAddress((void**)&x,    g_x);
    cudaGetSymbolAddress((void**)&y,    g_y);
    cudaGetSymbolAddress((void**)&y2,   g_y2);
    cudaGetSymbolAddress((void**)&z,    g_z);
    cudaGetSymbolAddress((void**)&h,    g_h);
    cudaGetSymbolAddress((void**)&cs,   g_colsum);
    cudaGetSymbolAddress((void**)&cq,   g_colsq);
    cudaGetSymbolAddress((void**)&aArr, g_aArr);
    cudaGetSymbolAddress((void**)&cArr, g_cArr);
    cudaGetSymbolAddress((void**)&bthi, g_bthi);
    cudaGetSymbolAddress((void**)&btlo, g_btlo);

    const int GEMM_SMEM = 4 * 128 * SMP * 2;   // 139264 B
    cudaFuncSetAttribute(gemm_mma_kernel,
                         cudaFuncAttributeMaxDynamicSharedMemorySize, GEMM_SMEM);

    const int EW_GRID = (NN * (DD / 4) + 255) / 256;   // 6250
    const int SC_GRID = (EE * 32 + 255) / 256;         // 75000 (1 warp/edge)
    const int ST_GRID = 250;

    prep_kernel<<<EW_GRID, 256>>>(h_in, x, cs, cq);

    for (int i = 0; i < LL; i++) {
        const float* hsrc = (i == 0) ? h_in : h;
        scatter_kernel<<<SC_GRID, 256>>>(hsrc, src, dst, w, x);

        wprep_kernel<<<64, 256>>>(W0s + i * DD * DD, bthi, btlo);
        gemm_mma_kernel<<<MTILES, 256, GEMM_SMEM>>>(x, bthi, btlo, y, nullptr, nullptr, 0);
        stats_kernel<<<ST_GRID, 256>>>(y, cs, cq);
        finalize_kernel<<<1, 128>>>(bn1g + i * DD, bn1b + i * DD, aArr, cArr, cs, cq);

        wprep_kernel<<<64, 256>>>(W1s + i * DD * DD, bthi, btlo);
        gemm_mma_kernel<<<MTILES, 256, GEMM_SMEM>>>(y, bthi, btlo, y2, aArr, cArr, 1);
        stats_kernel<<<ST_GRID, 256>>>(y2, cs, cq);
        finalize_kernel<<<1, 128>>>(bn2g + i * DD, bn2b + i * DD, aArr, cArr, cs, cq);

        zrelu_kernel<<<ST_GRID, 256>>>(y2, aArr, cArr, z, cs, cq);
        finalize_kernel<<<1, 128>>>(bn3g + i * DD, bn3b + i * DD, aArr, cArr, cs, cq);

        int last = (i == LL - 1);
        apply_kernel<<<EW_GRID, 256>>>(z, aArr, cArr,
                                       last ? (float*)d_out : h,
                                       last ? nullptr : x,
                                       last ? 0 : 1);
    }
}

// round 4
// speedup vs baseline: 1.9954x; 1.2471x over previous
#include <cuda_runtime.h>
#include <cuda_bf16.h>
#include <cstdint>
#include <math.h>

// Problem constants
#define NN 50000
#define EE 600000
#define DD 128
#define LL 3
#define GTILES 782            // ceil(50000/64)
#define NPAD (GTILES * 64)    // 50048
#define SMP 136               // smem row stride (bf16): conflict-free ldmatrix
#define NBLK 98               // ceil(NN/512) scan blocks

// ---------------- device scratch (static; no runtime alloc) ----------------
__device__ float g_x [NPAD * DD];
__device__ float g_y [NPAD * DD];
__device__ float g_y2[NPAD * DD];
__device__ float g_h [NPAD * DD];
__device__ float g_cs[DD], g_cq[DD];
__device__ float g_a1[DD], g_c1[DD], g_a2[DD], g_c2[DD], g_a3[DD], g_c3[DD];
__device__ __nv_bfloat16 g_bthi[LL * 2 * DD * DD];
__device__ __nv_bfloat16 g_btlo[LL * 2 * DD * DD];
__device__ int  g_countArr[NN];
__device__ int  g_startArr[NN];
__device__ int  g_curArr  [NN];
__device__ int  g_bsum[NBLK];
__device__ int  g_boff[NBLK];
__device__ int2 g_ssw[EE];            // (src, w bits) grouped by dst

// ---------------- warp-mma helpers ----------------
__device__ __forceinline__ uint32_t smem_u32(const void* p) {
    uint32_t a;
    asm("{ .reg .u64 t; cvta.to.shared.u64 t, %1; cvt.u32.u64 %0, t; }" : "=r"(a) : "l"(p));
    return a;
}
__device__ __forceinline__ void ldsm_x4(uint32_t* r, uint32_t addr) {
    asm volatile("ldmatrix.sync.aligned.m8n8.x4.shared.b16 {%0,%1,%2,%3}, [%4];"
                 : "=r"(r[0]), "=r"(r[1]), "=r"(r[2]), "=r"(r[3]) : "r"(addr));
}
__device__ __forceinline__ void mma_bf16(float* d, const uint32_t* a, const uint32_t* b) {
    asm volatile("mma.sync.aligned.m16n8k16.row.col.f32.bf16.bf16.f32 "
                 "{%0,%1,%2,%3}, {%4,%5,%6,%7}, {%8,%9}, {%0,%1,%2,%3};"
                 : "+f"(d[0]), "+f"(d[1]), "+f"(d[2]), "+f"(d[3])
                 : "r"(a[0]), "r"(a[1]), "r"(a[2]), "r"(a[3]),
                   "r"(b[0]), "r"(b[1]));
}

// ---------------- CSR build ----------------
__global__ void zero_kernel(int* cnt, float* cs, float* cq) {
    int i = blockIdx.x * blockDim.x + threadIdx.x;
    if (i < NN) cnt[i] = 0;
    if (i < DD) { cs[i] = 0.f; cq[i] = 0.f; }
}
__global__ void hist_kernel(const int* __restrict__ dst, int* cnt) {
    int e = blockIdx.x * blockDim.x + threadIdx.x;
    if (e < EE) atomicAdd(cnt + __ldg(dst + e), 1);
}
__global__ void scan1_kernel(const int* __restrict__ cnt, int* start, int* bsum) {
    __shared__ int sm[512];
    int t = threadIdx.x, idx = blockIdx.x * 512 + t;
    int v = (idx < NN) ? cnt[idx] : 0;
    sm[t] = v; __syncthreads();
    int x = v;
    for (int d = 1; d < 512; d <<= 1) {
        int y = (t >= d) ? sm[t - d] : 0;
        __syncthreads();
        x += y; sm[t] = x; __syncthreads();
    }
    if (idx < NN) start[idx] = x - v;
    if (t == 511) bsum[blockIdx.x] = x;
}
__global__ void scan2_kernel(const int* __restrict__ bsum, int* boff) {
    __shared__ int sm[128];
    int t = threadIdx.x;
    int v = (t < NBLK) ? bsum[t] : 0;
    sm[t] = v; __syncthreads();
    int x = v;
    for (int d = 1; d < 128; d <<= 1) {
        int y = (t >= d) ? sm[t - d] : 0;
        __syncthreads();
        x += y; sm[t] = x; __syncthreads();
    }
    if (t < NBLK) boff[t] = x - v;
}
__global__ void scan3_kernel(int* start, const int* __restrict__ boff, int* cur) {
    int i = blockIdx.x * blockDim.x + threadIdx.x;
    if (i >= NN) return;
    int s = start[i] + boff[i >> 9];
    start[i] = s; cur[i] = s;
}
__global__ void fill_kernel(const int* __restrict__ src, const int* __restrict__ dst,
                            const float* __restrict__ w, int* cur, int2* ssw) {
    int e = blockIdx.x * blockDim.x + threadIdx.x;
    if (e >= EE) return;
    int d = __ldg(dst + e);
    int slot = atomicAdd(cur + d, 1);
    ssw[slot] = make_int2(__ldg(src + e), __float_as_int(__ldg(w + e)));
}

// x[d] = h[d] + sum_e w*h[src]. One warp per node; lane = 4 feature floats.
__global__ void __launch_bounds__(256) gather_kernel(
    const float* __restrict__ hprev, const int* __restrict__ start,
    const int* __restrict__ cnt, const int2* __restrict__ ssw,
    float* __restrict__ x)
{
    int d = (blockIdx.x * blockDim.x + threadIdx.x) >> 5;
    int l = threadIdx.x & 31;
    if (d >= NN) return;
    int st  = __ldg(start + d);
    int deg = __ldg(cnt + d);
    float4 acc = *(const float4*)(hprev + (size_t)d * DD + l * 4);
    for (int j = 0; j < deg; j++) {
        int2 p = __ldg(ssw + st + j);
        float we = __int_as_float(p.y);
        float4 hv = *(const float4*)(hprev + (size_t)p.x * DD + l * 4);
        acc.x = fmaf(we, hv.x, acc.x);
        acc.y = fmaf(we, hv.y, acc.y);
        acc.z = fmaf(we, hv.z, acc.z);
        acc.w = fmaf(we, hv.w, acc.w);
    }
    *(float4*)(x + (size_t)d * DD + l * 4) = acc;
}

// All 6 weight matrices -> transposed hi/lo bf16 splits, once per call.
__global__ void wprep_all_kernel(const float* __restrict__ W0s, const float* __restrict__ W1s,
                                 __nv_bfloat16* __restrict__ bhi, __nv_bfloat16* __restrict__ blo)
{
    int idx = blockIdx.x * blockDim.x + threadIdx.x;
    if (idx >= 6 * DD * DD) return;
    int m2 = idx >> 14, r = idx & 16383;
    int k = r >> 7, n = r & 127;
    int layer = m2 >> 1, which = m2 & 1;
    const float* W = (which ? W1s : W0s) + layer * DD * DD;
    float v = W[r];
    __nv_bfloat16 h = __float2bfloat16(v);
    __nv_bfloat16 lo = __float2bfloat16(v - __bfloat162float(h));
    bhi[m2 * DD * DD + n * DD + k] = h;
    blo[m2 * DD * DD + n * DD + k] = lo;
}

// C[64-tile,128] = act(A) @ W, mma.sync bf16 hi/lo 3-pass, fused column stats.
__global__ void __launch_bounds__(256, 2) gemm_mma_kernel(
    const float* __restrict__ A,
    const __nv_bfloat16* __restrict__ Bhi, const __nv_bfloat16* __restrict__ Blo,
    float* __restrict__ C,
    const float* __restrict__ aAff, const float* __restrict__ cAff, int useAffine,
    float* __restrict__ statS, float* __restrict__ statQ)
{
    extern __shared__ __align__(16) char dyn[];
    __nv_bfloat16* sAhi = (__nv_bfloat16*)dyn;
    __nv_bfloat16* sAlo = sAhi + 64 * SMP;
    __nv_bfloat16* sBhi = sAlo + 64 * SMP;
    __nv_bfloat16* sBlo = sBhi + 128 * SMP;
    __shared__ float colS[DD], colQ[DD];

    const int t = threadIdx.x, w = t >> 5, l = t & 31;
    const int mBase = blockIdx.x * 64;

    if (t < DD) { colS[t] = 0.f; colQ[t] = 0.f; }

    // stage A: 64 rows fp32 -> (affine+relu) -> bf16 hi/lo
    float4 aa, cc;
    if (useAffine) { aa = ((const float4*)aAff)[l]; cc = ((const float4*)cAff)[l]; }
#pragma unroll
    for (int it = 0; it < 8; it++) {
        int row = it * 8 + w;
        float4 v = ((const float4*)(A + (size_t)(mBase + row) * DD))[l];
        if (useAffine) {
            v.x = fmaxf(fmaf(v.x, aa.x, cc.x), 0.f);
            v.y = fmaxf(fmaf(v.y, aa.y, cc.y), 0.f);
            v.z = fmaxf(fmaf(v.z, aa.z, cc.z), 0.f);
            v.w = fmaxf(fmaf(v.w, aa.w, cc.w), 0.f);
        }
        __nv_bfloat162 h01 = __floats2bfloat162_rn(v.x, v.y);
        __nv_bfloat162 h23 = __floats2bfloat162_rn(v.z, v.w);
        __nv_bfloat162 l01 = __floats2bfloat162_rn(v.x - __low2float(h01), v.y - __high2float(h01));
        __nv_bfloat162 l23 = __floats2bfloat162_rn(v.z - __low2float(h23), v.w - __high2float(h23));
        int off = row * SMP + l * 4;
        *(uint2*)(sAhi + off) = make_uint2(*(uint32_t*)&h01, *(uint32_t*)&h23);
        *(uint2*)(sAlo + off) = make_uint2(*(uint32_t*)&l01, *(uint32_t*)&l23);
    }
    // stage B: 128 n-rows, pre-split bf16 W^T[n][k]
#pragma unroll
    for (int it = 0; it < 16; it++) {
        int row = it * 8 + w;
        uint2 hv = ((const uint2*)(Bhi + (size_t)row * DD))[l];
        uint2 lv = ((const uint2*)(Blo + (size_t)row * DD))[l];
        int off = row * SMP + l * 4;
        *(uint2*)(sBhi + off) = hv;
        *(uint2*)(sBlo + off) = lv;
    }
    __syncthreads();

    // warp tile: 16(M) x 64(N); 8 n-subtiles of n8
    const int wm = (w >> 1) * 16;
    const int wn = (w & 1) * 64;
    float acc[8][4];
#pragma unroll
    for (int i = 0; i < 8; i++)
#pragma unroll
        for (int j = 0; j < 4; j++) acc[i][j] = 0.f;

    const int arow = wm + (l & 15);
    const int acol = (l >> 4) << 3;
    const int browb = wn + ((l >> 4) & 1) * 8 + (l & 7);   // paired-n ldsm.x4
    const int bcol  = ((l >> 3) & 1) << 3;

#pragma unroll
    for (int pass = 0; pass < 3; pass++) {
        const __nv_bfloat16* pA = (pass == 2) ? sAlo : sAhi;
        const __nv_bfloat16* pB = (pass == 1) ? sBlo : sBhi;
#pragma unroll
        for (int kc = 0; kc < 8; kc++) {
            const int k0 = kc * 16;
            uint32_t afr[4];
            ldsm_x4(afr, smem_u32(pA + arow * SMP + k0 + acol));
#pragma unroll
            for (int sn2 = 0; sn2 < 4; sn2++) {
                uint32_t bfr[4];
                ldsm_x4(bfr, smem_u32(pB + (browb + sn2 * 16) * SMP + k0 + bcol));
                mma_bf16(acc[sn2 * 2 + 0], afr, bfr + 0);
                mma_bf16(acc[sn2 * 2 + 1], afr, bfr + 2);
            }
        }
    }

    // epilogue: store + fused column stats (mask pad rows)
    const int g = l >> 2, tq = l & 3;
    const int row0 = mBase + wm + g;
    const float m0 = (row0 < NN) ? 1.f : 0.f;
    const float m1 = (row0 + 8 < NN) ? 1.f : 0.f;
#pragma unroll
    for (int sn = 0; sn < 8; sn++) {
        int col = wn + sn * 8 + tq * 2;
        float* p0 = C + (size_t)row0 * DD + col;
        *(float2*)p0            = make_float2(acc[sn][0], acc[sn][1]);
        *(float2*)(p0 + 8 * DD) = make_float2(acc[sn][2], acc[sn][3]);
        float v0 = m0 * acc[sn][0], v1 = m0 * acc[sn][1];
        float v2 = m1 * acc[sn][2], v3 = m1 * acc[sn][3];
        float cs0 = v0 + v2, cs1 = v1 + v3;
        float cq0 = v0 * v0 + v2 * v2, cq1 = v1 * v1 + v3 * v3;
#pragma unroll
        for (int dlt = 16; dlt >= 4; dlt >>= 1) {
            cs0 += __shfl_down_sync(0xffffffffu, cs0, dlt);
            cs1 += __shfl_down_sync(0xffffffffu, cs1, dlt);
            cq0 += __shfl_down_sync(0xffffffffu, cq0, dlt);
            cq1 += __shfl_down_sync(0xffffffffu, cq1, dlt);
        }
        if (l < 4) {
            int c0 = wn + sn * 8 + l * 2;
            atomicAdd(&colS[c0], cs0);  atomicAdd(&colS[c0 + 1], cs1);
            atomicAdd(&colQ[c0], cq0);  atomicAdd(&colQ[c0 + 1], cq1);
        }
    }
    __syncthreads();
    if (t < DD) {
        atomicAdd(statS + t, colS[t]);
        atomicAdd(statQ + t, colQ[t]);
    }
}

// Convert stats + (g, b) into per-column affine (a, c); reset stats.
__global__ void finalize_kernel(const float* __restrict__ g, const float* __restrict__ b,
                                float* __restrict__ aOut, float* __restrict__ cOut,
                                float* __restrict__ cs, float* __restrict__ cq)
{
    int c = threadIdx.x;
    const float invN = 1.f / (float)NN;
    float mean = cs[c] * invN;
    float var  = cq[c] * invN - mean * mean;
    float a = g[c] * rsqrtf(var + 1e-5f);
    aOut[c] = a;
    cOut[c] = b[c] - mean * a;
    cs[c] = 0.f; cq[c] = 0.f;
}

// stats of relu(y2*a + c) -- no store.
__global__ void __launch_bounds__(256) zstats_kernel(const float* __restrict__ y2,
                                                     const float* __restrict__ aA,
                                                     const float* __restrict__ cA,
                                                     float* __restrict__ cs,
                                                     float* __restrict__ cq)
{
    __shared__ float shS[8][DD];
    __shared__ float shQ[8][DD];
    const int t = threadIdx.x;
    const int c4 = (t & 31) * 4;
    const int rg = t >> 5;
    float4 a = *(const float4*)(aA + c4);
    float4 c = *(const float4*)(cA + c4);
    float4 s = make_float4(0.f, 0.f, 0.f, 0.f), q = make_float4(0.f, 0.f, 0.f, 0.f);
    for (int m = blockIdx.x * 8 + rg; m < NN; m += gridDim.x * 8) {
        float4 v = *(const float4*)(y2 + (size_t)m * DD + c4);
        v.x = fmaxf(fmaf(v.x, a.x, c.x), 0.f);
        v.y = fmaxf(fmaf(v.y, a.y, c.y), 0.f);
        v.z = fmaxf(fmaf(v.z, a.z, c.z), 0.f);
        v.w = fmaxf(fmaf(v.w, a.w, c.w), 0.f);
        s.x += v.x; s.y += v.y; s.z += v.z; s.w += v.w;
        q.x += v.x * v.x; q.y += v.y * v.y; q.z += v.z * v.z; q.w += v.w * v.w;
    }
    *(float4*)&shS[rg][c4] = s;
    *(float4*)&shQ[rg][c4] = q;
    __syncthreads();
    if (t < DD) {
        float ts = 0.f, tqv = 0.f;
#pragma unroll
        for (int i = 0; i < 8; i++) { ts += shS[i][t]; tqv += shQ[i][t]; }
        atomicAdd(cs + t, ts);
        atomicAdd(cq + t, tqv);
    }
}

// out = bn3(relu(bn2(y2))) with optional final relu (both affines applied here).
__global__ void apply_kernel(const float* __restrict__ y2,
                             const float* __restrict__ a2, const float* __restrict__ c2,
                             const float* __restrict__ a3, const float* __restrict__ c3,
                             float* __restrict__ out, int doRelu)
{
    int gid = blockIdx.x * blockDim.x + threadIdx.x;
    if (gid >= NN * (DD / 4)) return;
    int col4 = (gid & (DD / 4 - 1)) << 2;
    float4 v = ((const float4*)y2)[gid];
    float4 A2 = *(const float4*)(a2 + col4);
    float4 C2 = *(const float4*)(c2 + col4);
    float4 A3 = *(const float4*)(a3 + col4);
    float4 C3 = *(const float4*)(c3 + col4);
    v.x = fmaxf(fmaf(v.x, A2.x, C2.x), 0.f);
    v.y = fmaxf(fmaf(v.y, A2.y, C2.y), 0.f);
    v.z = fmaxf(fmaf(v.z, A2.z, C2.z), 0.f);
    v.w = fmaxf(fmaf(v.w, A2.w, C2.w), 0.f);
    v.x = fmaf(v.x, A3.x, C3.x);
    v.y = fmaf(v.y, A3.y, C3.y);
    v.z = fmaf(v.z, A3.z, C3.z);
    v.w = fmaf(v.w, A3.w, C3.w);
    if (doRelu) {
        v.x = fmaxf(v.x, 0.f); v.y = fmaxf(v.y, 0.f);
        v.z = fmaxf(v.z, 0.f); v.w = fmaxf(v.w, 0.f);
    }
    ((float4*)out)[gid] = v;
}

// ---------------- launch ----------------
extern "C" void kernel_launch(void* const* d_in, const int* in_sizes, int n_in,
                              void* d_out, int out_size)
{
    const float* h_in = (const float*)d_in[0];
    const int*   edges= (const int*)  d_in[1];
    const float* w    = (const float*)d_in[2];
    const float* W0s  = (const float*)d_in[3];
    const float* W1s  = (const float*)d_in[4];
    const float* bn1g = (const float*)d_in[5];
    const float* bn1b = (const float*)d_in[6];
    const float* bn2g = (const float*)d_in[7];
    const float* bn2b = (const float*)d_in[8];
    const float* bn3g = (const float*)d_in[9];
    const float* bn3b = (const float*)d_in[10];
    const int* src = edges;
    const int* dst = edges + EE;

    float *x, *y, *y2, *h, *cs, *cq, *a1, *c1, *a2, *c2, *a3, *c3;
    __nv_bfloat16 *bthi, *btlo;
    int *cnt, *startA, *cur, *bsum, *boff;
    int2 *ssw;
    cudaGetSymbolAddress((void**)&x,    g_x);
    cudaGetSymbolAddress((void**)&y,    g_y);
    cudaGetSymbolAddress((void**)&y2,   g_y2);
    cudaGetSymbolAddress((void**)&h,    g_h);
    cudaGetSymbolAddress((void**)&cs,   g_cs);
    cudaGetSymbolAddress((void**)&cq,   g_cq);
    cudaGetSymbolAddress((void**)&a1,   g_a1);
    cudaGetSymbolAddress((void**)&c1,   g_c1);
    cudaGetSymbolAddress((void**)&a2,   g_a2);
    cudaGetSymbolAddress((void**)&c2,   g_c2);
    cudaGetSymbolAddress((void**)&a3,   g_a3);
    cudaGetSymbolAddress((void**)&c3,   g_c3);
    cudaGetSymbolAddress((void**)&bthi, g_bthi);
    cudaGetSymbolAddress((void**)&btlo, g_btlo);
    cudaGetSymbolAddress((void**)&cnt,  g_countArr);
    cudaGetSymbolAddress((void**)&startA, g_startArr);
    cudaGetSymbolAddress((void**)&cur,  g_curArr);
    cudaGetSymbolAddress((void**)&bsum, g_bsum);
    cudaGetSymbolAddress((void**)&boff, g_boff);
    cudaGetSymbolAddress((void**)&ssw,  g_ssw);

    const int GEMM_SMEM = (64 + 64 + 128 + 128) * SMP * 2;   // 104448 B
    cudaFuncSetAttribute(gemm_mma_kernel,
                         cudaFuncAttributeMaxDynamicSharedMemorySize, GEMM_SMEM);

    const int EGRID = (EE + 255) / 256;
    const int NGRID = (NN + 255) / 256;
    const int WGRID = (NN * 32 + 255) / 256;   // 6250 (warp per node)

    // CSR build (once per call; reused by all 3 layers)
    zero_kernel <<<NGRID, 256>>>(cnt, cs, cq);
    hist_kernel <<<EGRID, 256>>>(dst, cnt);
    scan1_kernel<<<NBLK, 512>>>(cnt, startA, bsum);
    scan2_kernel<<<1, 128>>>(bsum, boff);
    scan3_kernel<<<NGRID, 256>>>(startA, boff, cur);
    fill_kernel <<<EGRID, 256>>>(src, dst, w, cur, ssw);
    wprep_all_kernel<<<(6 * DD * DD + 255) / 256, 256>>>(W0s, W1s, bthi, btlo);

    for (int i = 0; i < LL; i++) {
        const float* hsrc = (i == 0) ? h_in : h;
        gather_kernel<<<WGRID, 256>>>(hsrc, startA, cnt, ssw, x);

        const __nv_bfloat16* b0h = bthi + (i * 2 + 0) * DD * DD;
        const __nv_bfloat16* b0l = btlo + (i * 2 + 0) * DD * DD;
        const __nv_bfloat16* b1h = bthi + (i * 2 + 1) * DD * DD;
        const __nv_bfloat16* b1l = btlo + (i * 2 + 1) * DD * DD;

        gemm_mma_kernel<<<GTILES, 256, GEMM_SMEM>>>(x, b0h, b0l, y,
                                                    nullptr, nullptr, 0, cs, cq);
        finalize_kernel<<<1, 128>>>(bn1g + i * DD, bn1b + i * DD, a1, c1, cs, cq);

        gemm_mma_kernel<<<GTILES, 256, GEMM_SMEM>>>(y, b1h, b1l, y2,
                                                    a1, c1, 1, cs, cq);
        finalize_kernel<<<1, 128>>>(bn2g + i * DD, bn2b + i * DD, a2, c2, cs, cq);

        zstats_kernel<<<250, 256>>>(y2, a2, c2, cs, cq);
        finalize_kernel<<<1, 128>>>(bn3g + i * DD, bn3b + i * DD, a3, c3, cs, cq);

        int last = (i == LL - 1);
        apply_kernel<<<WGRID, 256>>>(y2, a2, c2, a3, c3,
                                     last ? (float*)d_out : h, last ? 0 : 1);
    }
}